// round 1
// baseline (speedup 1.0000x reference)
#include <cuda_runtime.h>
#include <cstdint>

#define NHEADS 16
#define HID    1024
#define TT     2048
#define BB     32

typedef unsigned long long ull;

// ---------------- device scratch (no allocations allowed) ----------------
__device__ float g_wq[NHEADS * HID];                  // folded q @ kv_w (k half), incl. scale
__device__ float g_c[NHEADS];                         // folded q @ kv_b (k half)
__device__ float g_logits[BB * NHEADS * TT];          // 4 MB; reused in-place as attn
__device__ float g_partial[16 * BB * NHEADS * HID];   // 32 MB pass-2 partials
__device__ float g_outv[BB * HID];                    // pooled, v-projected [B, H]
__device__ float g_fpart[8 * BB * HID];               // final-GEMM c-slice partials

// packed f32x2 FMA (Blackwell; ptxas never emits FFMA2 from C++)
#define FMA2(c, a, b) asm("fma.rn.f32x2 %0, %1, %2, %0;" : "+l"(c) : "l"(a), "l"(b))

static __device__ __forceinline__ float f2_lo(ull v) { return __uint_as_float((unsigned)(v & 0xffffffffull)); }
static __device__ __forceinline__ float f2_hi(ull v) { return __uint_as_float((unsigned)(v >> 32)); }

// ---------------- kernel 1: fold query into kv_w (k half) ----------------
__global__ void k_wq(const float* __restrict__ q,
                     const float* __restrict__ kvw,
                     const float* __restrict__ kvb) {
    int w = blockIdx.x * (blockDim.x >> 5) + (threadIdx.x >> 5);
    int lane = threadIdx.x & 31;
    if (w < NHEADS * HID) {
        int h = w & (NHEADS - 1);
        int i = w >> 4;
        const float* wr = kvw + (size_t)i * (2 * HID) + h * 64;
        const float* qr = q + h * 64;
        float s = qr[lane] * wr[lane] + qr[lane + 32] * wr[lane + 32];
        #pragma unroll
        for (int o = 16; o; o >>= 1) s += __shfl_xor_sync(0xffffffffu, s, o);
        if (lane == 0) g_wq[h * HID + i] = 0.125f * s;   // scale = 1/sqrt(64)
    }
    if (blockIdx.x == 0 && threadIdx.x < NHEADS) {
        int h = threadIdx.x;
        float s = 0.f;
        for (int d = 0; d < 64; d++) s += q[h * 64 + d] * kvb[h * 64 + d];
        g_c[h] = 0.125f * s;
    }
}

// ---------------- kernel 2: logits[b,h,j] = hid[b,j,:] . wq[h,:] + c[h] ----------------
// One thread owns one j-row entirely; wq chunk staged in shared, read as
// warp-uniform broadcasts; hidden read as two LDG.128 per 32B sector.
__global__ void __launch_bounds__(128) k_logits(const float* __restrict__ hid) {
    __shared__ ull wq_s[NHEADS][256];   // 512-float k-chunk per head, 32 KB
    int tid = threadIdx.x;
    size_t j = (size_t)blockIdx.x * 128 + tid;          // 0..65535
    const float* hrow = hid + j * HID;
    int b  = (int)(j >> 11);
    int jj = (int)(j & 2047);

    ull acc[NHEADS];
    #pragma unroll
    for (int h = 0; h < NHEADS; h++) acc[h] = 0ull;

    for (int kc = 0; kc < HID; kc += 512) {
        __syncthreads();
        for (int t = tid; t < 2048; t += 128) {          // 16 heads * 128 float4
            int h  = t >> 7;
            int kk = t & 127;
            float4 v = *(const float4*)(g_wq + h * HID + kc + kk * 4);
            ((float4*)wq_s[h])[kk] = v;
        }
        __syncthreads();
        #pragma unroll 2
        for (int k = 0; k < 512; k += 8) {
            ulonglong2 ha = *(const ulonglong2*)(hrow + kc + k);
            ulonglong2 hb = *(const ulonglong2*)(hrow + kc + k + 4);
            #pragma unroll
            for (int h = 0; h < NHEADS; h++) {
                ulonglong2 w0 = *(const ulonglong2*)&wq_s[h][(k >> 1)];
                ulonglong2 w1 = *(const ulonglong2*)&wq_s[h][(k >> 1) + 2];
                FMA2(acc[h], ha.x, w0.x);
                FMA2(acc[h], ha.y, w0.y);
                FMA2(acc[h], hb.x, w1.x);
                FMA2(acc[h], hb.y, w1.y);
            }
        }
    }
    #pragma unroll
    for (int h = 0; h < NHEADS; h++) {
        g_logits[((size_t)(b * NHEADS + h)) * TT + jj] = f2_lo(acc[h]) + f2_hi(acc[h]) + g_c[h];
    }
}

// ---------------- kernel 3: softmax over j per (b,h), mask-aware, in-place ----------------
__global__ void __launch_bounds__(256) k_softmax(const int* __restrict__ mask) {
    int bh = blockIdx.x;
    int b  = bh >> 4;
    float* row = g_logits + (size_t)bh * TT;
    const int* mrow = mask + (size_t)b * TT;
    int tid = threadIdx.x;

    float x[8];
    float mx = -1e30f;
    #pragma unroll
    for (int r = 0; r < 8; r++) {
        int j = tid + r * 256;
        float v = row[j];
        if (mrow[j] == 0) v = -1e30f;
        x[r] = v;
        mx = fmaxf(mx, v);
    }
    __shared__ float red[8];
    #pragma unroll
    for (int o = 16; o; o >>= 1) mx = fmaxf(mx, __shfl_xor_sync(0xffffffffu, mx, o));
    if ((tid & 31) == 0) red[tid >> 5] = mx;
    __syncthreads();
    mx = red[0];
    #pragma unroll
    for (int w = 1; w < 8; w++) mx = fmaxf(mx, red[w]);

    float sum = 0.f;
    #pragma unroll
    for (int r = 0; r < 8; r++) { float e = __expf(x[r] - mx); x[r] = e; sum += e; }
    #pragma unroll
    for (int o = 16; o; o >>= 1) sum += __shfl_xor_sync(0xffffffffu, sum, o);
    __syncthreads();
    if ((tid & 31) == 0) red[tid >> 5] = sum;
    __syncthreads();
    sum = red[0] + red[1] + red[2] + red[3] + red[4] + red[5] + red[6] + red[7];
    float inv = __fdividef(1.f, sum);
    #pragma unroll
    for (int r = 0; r < 8; r++) row[tid + r * 256] = x[r] * inv;
}

// ---------------- kernel 4: partial pooled[b,h,:] = sum_j attn * hid over a j-slice ----------------
// Thread owns 4 consecutive i; attn staged duplicated as f32x2 for direct FFMA2 broadcast.
__global__ void __launch_bounds__(256) k_pool(const float* __restrict__ hid) {
    int slice = blockIdx.x;       // 16 slices of 128 j
    int b     = blockIdx.y;
    int j0    = slice * 128;
    __shared__ ull attn_s[128][NHEADS];   // 16 KB, value duplicated in both halves
    int tid = threadIdx.x;

    for (int t = tid; t < 128 * NHEADS; t += 256) {
        int jloc = t & 127;
        int h    = t >> 7;
        float a = g_logits[((size_t)(b * NHEADS + h)) * TT + j0 + jloc];
        unsigned u = __float_as_uint(a);
        attn_s[jloc][h] = ((ull)u << 32) | u;
    }
    __syncthreads();

    int i0 = tid * 4;
    const float* hbase = hid + ((size_t)b * TT + j0) * HID + i0;
    ull acc[32];
    #pragma unroll
    for (int t = 0; t < 32; t++) acc[t] = 0ull;

    for (int j = 0; j < 128; j++) {
        ulonglong2 hv = *(const ulonglong2*)(hbase + (size_t)j * HID);
        #pragma unroll
        for (int h = 0; h < NHEADS; h++) {
            ull a = attn_s[j][h];
            FMA2(acc[2 * h],     a, hv.x);
            FMA2(acc[2 * h + 1], a, hv.y);
        }
    }

    float* pbase = g_partial + (((size_t)slice * BB + b) * NHEADS) * HID + i0;
    #pragma unroll
    for (int h = 0; h < NHEADS; h++) {
        float4 o;
        o.x = f2_lo(acc[2 * h]);     o.y = f2_hi(acc[2 * h]);
        o.z = f2_lo(acc[2 * h + 1]); o.w = f2_hi(acc[2 * h + 1]);
        *(float4*)(pbase + (size_t)h * HID) = o;
    }
}

// ---------------- kernel 5: reduce partials + per-head V projection ----------------
// outv[b, h*64+d] = pooled[b,h,:] . kv_w[:, 1024 + h*64+d] + kv_b[1024 + h*64+d]
__global__ void __launch_bounds__(256) k_outv(const float* __restrict__ kvw,
                                              const float* __restrict__ kvb) {
    int bh = blockIdx.x;
    int b = bh >> 4;
    int h = bh & 15;
    __shared__ float pooled_s[HID];
    __shared__ float red[4][64];
    int tid = threadIdx.x;
    int i0 = tid * 4;

    float4 s = make_float4(0.f, 0.f, 0.f, 0.f);
    for (int sl = 0; sl < 16; sl++) {
        float4 v = *(const float4*)(g_partial + (((size_t)sl * BB + b) * NHEADS + h) * HID + i0);
        s.x += v.x; s.y += v.y; s.z += v.z; s.w += v.w;
    }
    *(float4*)(pooled_s + i0) = s;
    __syncthreads();

    int d  = tid & 63;
    int qq = tid >> 6;
    const float* wcol = kvw + HID + h * 64 + d;   // v half; row stride 2*HID
    float acc = 0.f;
    int ibeg = qq * 256;
    #pragma unroll 4
    for (int i = ibeg; i < ibeg + 256; i++)
        acc += pooled_s[i] * __ldg(wcol + (size_t)i * (2 * HID));
    red[qq][d] = acc;
    __syncthreads();
    if (tid < 64)
        g_outv[b * HID + h * 64 + tid] =
            red[0][tid] + red[1][tid] + red[2][tid] + red[3][tid] + kvb[HID + h * 64 + tid];
}

// ---------------- kernel 6: final GEMM [32,1024] x [1024,1024], c-sliced ----------------
__global__ void __launch_bounds__(256) k_final(const float* __restrict__ outw) {
    int p0 = blockIdx.x * 128;
    int c0 = blockIdx.y * 128;
    __shared__ float outv_s[32][128];
    int tid = threadIdx.x;
    for (int t = tid; t < 32 * 128; t += 256) {
        int bb2 = t >> 7;
        int cc  = t & 127;
        outv_s[bb2][cc] = g_outv[bb2 * HID + c0 + cc];
    }
    __syncthreads();

    int p   = tid & 127;
    int bh2 = tid >> 7;   // 0/1 -> 16 batches each
    float acc[16];
    #pragma unroll
    for (int n = 0; n < 16; n++) acc[n] = 0.f;

    for (int cc = 0; cc < 128; cc++) {
        float w = __ldg(outw + (size_t)(c0 + cc) * 1024 + p0 + p);
        #pragma unroll
        for (int n = 0; n < 16; n++) acc[n] += outv_s[bh2 * 16 + n][cc] * w;
    }
    #pragma unroll
    for (int n = 0; n < 16; n++)
        g_fpart[((size_t)blockIdx.y * BB + bh2 * 16 + n) * 1024 + p0 + p] = acc[n];
}

__global__ void k_finred(const float* __restrict__ outb, float* __restrict__ out) {
    int idx = blockIdx.x * 256 + threadIdx.x;   // 32768 outputs
    int b = idx >> 10;
    int p = idx & 1023;
    float s = outb[p];
    #pragma unroll
    for (int cs = 0; cs < 8; cs++) s += g_fpart[((size_t)cs * BB + b) * 1024 + p];
    out[idx] = s;
}

// ---------------- launch ----------------
extern "C" void kernel_launch(void* const* d_in, const int* in_sizes, int n_in,
                              void* d_out, int out_size) {
    const float* hid  = (const float*)d_in[0];
    const int*   mask = (const int*)  d_in[1];
    const float* kvw  = (const float*)d_in[2];
    const float* kvb  = (const float*)d_in[3];
    const float* outw = (const float*)d_in[4];
    const float* outb = (const float*)d_in[5];
    const float* q    = (const float*)d_in[6];
    float* out = (float*)d_out;

    k_wq     <<<2048, 256>>>(q, kvw, kvb);
    k_logits <<<512, 128>>>(hid);
    k_softmax<<<512, 256>>>(mask);
    k_pool   <<<dim3(16, 32), 256>>>(hid);
    k_outv   <<<512, 256>>>(kvw, kvb);
    k_final  <<<dim3(8, 8), 256>>>(outw);
    k_finred <<<128, 256>>>(outb, out);
}

// round 2
// speedup vs baseline: 1.1175x; 1.1175x over previous
#include <cuda_runtime.h>
#include <cstdint>

#define NHEADS 16
#define HID    1024
#define TT     2048
#define BB     32

typedef unsigned long long ull;

// ---------------- device scratch (no allocations allowed) ----------------
__device__ float g_wq[NHEADS * HID];                  // folded q @ kv_w (k half), incl. scale
__device__ float g_c[NHEADS];                         // folded q @ kv_b (k half)
__device__ float g_logits[BB * NHEADS * TT];          // 4 MB; reused in-place as attn
__device__ float g_partial[16 * BB * NHEADS * HID];   // 32 MB pass-2 partials
__device__ float g_outv[BB * HID];                    // pooled, v-projected [B, H]
__device__ float g_fpart[8 * BB * HID];               // final-GEMM c-slice partials

// packed f32x2 FMA (Blackwell; ptxas never emits FFMA2 from C++)
#define FMA2(c, a, b) asm("fma.rn.f32x2 %0, %1, %2, %0;" : "+l"(c) : "l"(a), "l"(b))

static __device__ __forceinline__ float f2_lo(ull v) { return __uint_as_float((unsigned)(v & 0xffffffffull)); }
static __device__ __forceinline__ float f2_hi(ull v) { return __uint_as_float((unsigned)(v >> 32)); }

// ---------------- kernel 1: fold query into kv_w (k half) ----------------
__global__ void k_wq(const float* __restrict__ q,
                     const float* __restrict__ kvw,
                     const float* __restrict__ kvb) {
    int w = blockIdx.x * (blockDim.x >> 5) + (threadIdx.x >> 5);
    int lane = threadIdx.x & 31;
    if (w < NHEADS * HID) {
        int h = w & (NHEADS - 1);
        int i = w >> 4;
        const float* wr = kvw + (size_t)i * (2 * HID) + h * 64;
        const float* qr = q + h * 64;
        float s = qr[lane] * wr[lane] + qr[lane + 32] * wr[lane + 32];
        #pragma unroll
        for (int o = 16; o; o >>= 1) s += __shfl_xor_sync(0xffffffffu, s, o);
        if (lane == 0) g_wq[h * HID + i] = 0.125f * s;   // scale = 1/sqrt(64)
    }
    if (blockIdx.x == 0 && threadIdx.x < NHEADS) {
        int h = threadIdx.x;
        float s = 0.f;
        for (int d = 0; d < 64; d++) s += q[h * 64 + d] * kvb[h * 64 + d];
        g_c[h] = 0.125f * s;
    }
}

// ---------------- kernel 2: logits[b,h,j] = hid[b,j,:] . wq[h,:] + c[h] ----------------
// 128 threads, each owning TWO j-rows 128 apart: wq LDS amortized over 2 rows.
// Per 8-k step: 4 LDG.128 + 32 LDS.128 + 128 FFMA2 (78% fma mix).
__global__ void __launch_bounds__(128) k_logits(const float* __restrict__ hid) {
    __shared__ ull wq_s[NHEADS][256];   // 512-float k-chunk per head (k-pairs), 32 KB
    int tid = threadIdx.x;
    size_t j0 = (size_t)blockIdx.x * 256 + tid;          // row A
    size_t j1 = j0 + 128;                                // row B
    const float* r0 = hid + j0 * HID;
    const float* r1 = hid + j1 * HID;

    ull acc0[NHEADS], acc1[NHEADS];
    #pragma unroll
    for (int h = 0; h < NHEADS; h++) { acc0[h] = 0ull; acc1[h] = 0ull; }

    for (int kc = 0; kc < HID; kc += 512) {
        __syncthreads();
        #pragma unroll
        for (int t = 0; t < 16; t++) {                   // 16 heads * 128 float4 over 128 thr
            int idx = t * 128 + tid;
            int h  = idx >> 7;
            int kk = idx & 127;
            float4 v = *(const float4*)(g_wq + h * HID + kc + kk * 4);
            ((float4*)wq_s[h])[kk] = v;
        }
        __syncthreads();
        #pragma unroll 2
        for (int k = 0; k < 512; k += 8) {
            ulonglong2 a0 = *(const ulonglong2*)(r0 + kc + k);
            ulonglong2 b0 = *(const ulonglong2*)(r0 + kc + k + 4);
            ulonglong2 a1 = *(const ulonglong2*)(r1 + kc + k);
            ulonglong2 b1 = *(const ulonglong2*)(r1 + kc + k + 4);
            #pragma unroll
            for (int h = 0; h < NHEADS; h++) {
                ulonglong2 w0 = *(const ulonglong2*)&wq_s[h][(k >> 1)];
                ulonglong2 w1 = *(const ulonglong2*)&wq_s[h][(k >> 1) + 2];
                FMA2(acc0[h], a0.x, w0.x);
                FMA2(acc0[h], a0.y, w0.y);
                FMA2(acc0[h], b0.x, w1.x);
                FMA2(acc0[h], b0.y, w1.y);
                FMA2(acc1[h], a1.x, w0.x);
                FMA2(acc1[h], a1.y, w0.y);
                FMA2(acc1[h], b1.x, w1.x);
                FMA2(acc1[h], b1.y, w1.y);
            }
        }
    }
    int bA  = (int)(j0 >> 11), jA = (int)(j0 & 2047);
    int bB  = (int)(j1 >> 11), jB = (int)(j1 & 2047);
    #pragma unroll
    for (int h = 0; h < NHEADS; h++) {
        float c = g_c[h];
        g_logits[((size_t)(bA * NHEADS + h)) * TT + jA] = f2_lo(acc0[h]) + f2_hi(acc0[h]) + c;
        g_logits[((size_t)(bB * NHEADS + h)) * TT + jB] = f2_lo(acc1[h]) + f2_hi(acc1[h]) + c;
    }
}

// ---------------- kernel 3: softmax over j per (b,h), mask-aware, in-place ----------------
__global__ void __launch_bounds__(256) k_softmax(const int* __restrict__ mask) {
    int bh = blockIdx.x;
    int b  = bh >> 4;
    float* row = g_logits + (size_t)bh * TT;
    const int* mrow = mask + (size_t)b * TT;
    int tid = threadIdx.x;

    float x[8];
    float mx = -1e30f;
    #pragma unroll
    for (int r = 0; r < 8; r++) {
        int j = tid + r * 256;
        float v = row[j];
        if (mrow[j] == 0) v = -1e30f;
        x[r] = v;
        mx = fmaxf(mx, v);
    }
    __shared__ float red[8];
    #pragma unroll
    for (int o = 16; o; o >>= 1) mx = fmaxf(mx, __shfl_xor_sync(0xffffffffu, mx, o));
    if ((tid & 31) == 0) red[tid >> 5] = mx;
    __syncthreads();
    mx = red[0];
    #pragma unroll
    for (int w = 1; w < 8; w++) mx = fmaxf(mx, red[w]);

    float sum = 0.f;
    #pragma unroll
    for (int r = 0; r < 8; r++) { float e = __expf(x[r] - mx); x[r] = e; sum += e; }
    #pragma unroll
    for (int o = 16; o; o >>= 1) sum += __shfl_xor_sync(0xffffffffu, sum, o);
    __syncthreads();
    if ((tid & 31) == 0) red[tid >> 5] = sum;
    __syncthreads();
    sum = red[0] + red[1] + red[2] + red[3] + red[4] + red[5] + red[6] + red[7];
    float inv = __fdividef(1.f, sum);
    #pragma unroll
    for (int r = 0; r < 8; r++) row[tid + r * 256] = x[r] * inv;
}

// ---------------- kernel 4: partial pooled[b,h,:] = sum_j attn * hid over a j-slice ----------------
// 128 threads, 8 i per thread. attn staged duplicated (f32x2) and read as
// LDS.128 head-pairs. Per j: 2 LDG.128 + 8 LDS.128 + 64 FFMA2 (86% fma mix).
// Depth-1 prefetch of the next j's hidden.
__global__ void __launch_bounds__(128) k_pool(const float* __restrict__ hid) {
    int slice = blockIdx.x;       // 16 slices of 128 j
    int b     = blockIdx.y;
    int j0    = slice * 128;
    __shared__ __align__(16) ull attn_s[128][NHEADS];   // 16 KB, value duplicated in both halves
    int tid = threadIdx.x;

    #pragma unroll
    for (int t = 0; t < 16; t++) {
        int idx = t * 128 + tid;
        int jloc = idx & 127;
        int h    = idx >> 7;
        float a = g_logits[((size_t)(b * NHEADS + h)) * TT + j0 + jloc];
        unsigned u = __float_as_uint(a);
        attn_s[jloc][h] = ((ull)u << 32) | u;
    }
    __syncthreads();

    int i0 = tid * 8;
    const float* hbase = hid + ((size_t)b * TT + j0) * HID + i0;

    ull acc[64];   // [h][4]  (8 i = 4 f32x2 per head)
    #pragma unroll
    for (int t = 0; t < 64; t++) acc[t] = 0ull;

    ulonglong2 c0 = *(const ulonglong2*)(hbase);
    ulonglong2 c1 = *(const ulonglong2*)(hbase + 4);

    for (int j = 0; j < 128; j++) {
        ulonglong2 u0 = c0, u1 = c1;
        if (j < 127) {
            c0 = *(const ulonglong2*)(hbase + (size_t)(j + 1) * HID);
            c1 = *(const ulonglong2*)(hbase + (size_t)(j + 1) * HID + 4);
        }
        #pragma unroll
        for (int p = 0; p < 8; p++) {                 // head pairs
            ulonglong2 ap = *(const ulonglong2*)&attn_s[j][2 * p];
            FMA2(acc[(2 * p) * 4 + 0], ap.x, u0.x);
            FMA2(acc[(2 * p) * 4 + 1], ap.x, u0.y);
            FMA2(acc[(2 * p) * 4 + 2], ap.x, u1.x);
            FMA2(acc[(2 * p) * 4 + 3], ap.x, u1.y);
            FMA2(acc[(2 * p + 1) * 4 + 0], ap.y, u0.x);
            FMA2(acc[(2 * p + 1) * 4 + 1], ap.y, u0.y);
            FMA2(acc[(2 * p + 1) * 4 + 2], ap.y, u1.x);
            FMA2(acc[(2 * p + 1) * 4 + 3], ap.y, u1.y);
        }
    }

    float* pbase = g_partial + (((size_t)slice * BB + b) * NHEADS) * HID + i0;
    #pragma unroll
    for (int h = 0; h < NHEADS; h++) {
        float4 o0, o1;
        o0.x = f2_lo(acc[h * 4 + 0]); o0.y = f2_hi(acc[h * 4 + 0]);
        o0.z = f2_lo(acc[h * 4 + 1]); o0.w = f2_hi(acc[h * 4 + 1]);
        o1.x = f2_lo(acc[h * 4 + 2]); o1.y = f2_hi(acc[h * 4 + 2]);
        o1.z = f2_lo(acc[h * 4 + 3]); o1.w = f2_hi(acc[h * 4 + 3]);
        *(float4*)(pbase + (size_t)h * HID)     = o0;
        *(float4*)(pbase + (size_t)h * HID + 4) = o1;
    }
}

// ---------------- kernel 5: reduce partials + per-head V projection ----------------
__global__ void __launch_bounds__(256) k_outv(const float* __restrict__ kvw,
                                              const float* __restrict__ kvb) {
    int bh = blockIdx.x;
    int b = bh >> 4;
    int h = bh & 15;
    __shared__ float pooled_s[HID];
    __shared__ float red[4][64];
    int tid = threadIdx.x;
    int i0 = tid * 4;

    float4 s = make_float4(0.f, 0.f, 0.f, 0.f);
    for (int sl = 0; sl < 16; sl++) {
        float4 v = *(const float4*)(g_partial + (((size_t)sl * BB + b) * NHEADS + h) * HID + i0);
        s.x += v.x; s.y += v.y; s.z += v.z; s.w += v.w;
    }
    *(float4*)(pooled_s + i0) = s;
    __syncthreads();

    int d  = tid & 63;
    int qq = tid >> 6;
    const float* wcol = kvw + HID + h * 64 + d;   // v half; row stride 2*HID
    float acc = 0.f;
    int ibeg = qq * 256;
    #pragma unroll 4
    for (int i = ibeg; i < ibeg + 256; i++)
        acc += pooled_s[i] * __ldg(wcol + (size_t)i * (2 * HID));
    red[qq][d] = acc;
    __syncthreads();
    if (tid < 64)
        g_outv[b * HID + h * 64 + tid] =
            red[0][tid] + red[1][tid] + red[2][tid] + red[3][tid] + kvb[HID + h * 64 + tid];
}

// ---------------- kernel 6: final GEMM [32,1024] x [1024,1024], c-sliced ----------------
__global__ void __launch_bounds__(256) k_final(const float* __restrict__ outw) {
    int p0 = blockIdx.x * 128;
    int c0 = blockIdx.y * 128;
    __shared__ float outv_s[32][128];
    int tid = threadIdx.x;
    for (int t = tid; t < 32 * 128; t += 256) {
        int bb2 = t >> 7;
        int cc  = t & 127;
        outv_s[bb2][cc] = g_outv[bb2 * HID + c0 + cc];
    }
    __syncthreads();

    int p   = tid & 127;
    int bh2 = tid >> 7;   // 0/1 -> 16 batches each
    float acc[16];
    #pragma unroll
    for (int n = 0; n < 16; n++) acc[n] = 0.f;

    for (int cc = 0; cc < 128; cc++) {
        float w = __ldg(outw + (size_t)(c0 + cc) * 1024 + p0 + p);
        #pragma unroll
        for (int n = 0; n < 16; n++) acc[n] += outv_s[bh2 * 16 + n][cc] * w;
    }
    #pragma unroll
    for (int n = 0; n < 16; n++)
        g_fpart[((size_t)blockIdx.y * BB + bh2 * 16 + n) * 1024 + p0 + p] = acc[n];
}

__global__ void k_finred(const float* __restrict__ outb, float* __restrict__ out) {
    int idx = blockIdx.x * 256 + threadIdx.x;   // 32768 outputs
    int b = idx >> 10;
    int p = idx & 1023;
    float s = outb[p];
    #pragma unroll
    for (int cs = 0; cs < 8; cs++) s += g_fpart[((size_t)cs * BB + b) * 1024 + p];
    out[idx] = s;
}

// ---------------- launch ----------------
extern "C" void kernel_launch(void* const* d_in, const int* in_sizes, int n_in,
                              void* d_out, int out_size) {
    const float* hid  = (const float*)d_in[0];
    const int*   mask = (const int*)  d_in[1];
    const float* kvw  = (const float*)d_in[2];
    const float* kvb  = (const float*)d_in[3];
    const float* outw = (const float*)d_in[4];
    const float* outb = (const float*)d_in[5];
    const float* q    = (const float*)d_in[6];
    float* out = (float*)d_out;

    k_wq     <<<2048, 256>>>(q, kvw, kvb);
    k_logits <<<256, 128>>>(hid);
    k_softmax<<<512, 256>>>(mask);
    k_pool   <<<dim3(16, 32), 128>>>(hid);
    k_outv   <<<512, 256>>>(kvw, kvb);
    k_final  <<<dim3(8, 8), 256>>>(outw);
    k_finred <<<128, 256>>>(outb, out);
}

// round 3
// speedup vs baseline: 1.2597x; 1.1273x over previous
#include <cuda_runtime.h>
#include <cstdint>

#define NHEADS 16
#define HID    1024
#define TT     2048
#define BB     32

typedef unsigned long long ull;

// ---------------- device scratch (no allocations allowed) ----------------
__device__ float g_wq[NHEADS * HID];                  // folded q @ kv_w (k half), incl. scale
__device__ float g_c[NHEADS];                         // folded q @ kv_b (k half)
__device__ float g_logits[BB * NHEADS * TT];          // 4 MB; reused in-place as attn
__device__ float g_partial[16 * BB * NHEADS * HID];   // 32 MB pass-2 partials
__device__ float g_outv[BB * HID];                    // pooled, v-projected [B, H]
__device__ float g_fpart[8 * BB * HID];               // final-GEMM c-slice partials

// packed f32x2 FMA (Blackwell; ptxas never emits FFMA2 from C++)
#define FMA2(c, a, b) asm("fma.rn.f32x2 %0, %1, %2, %0;" : "+l"(c) : "l"(a), "l"(b))

static __device__ __forceinline__ float f2_lo(ull v) { return __uint_as_float((unsigned)(v & 0xffffffffull)); }
static __device__ __forceinline__ float f2_hi(ull v) { return __uint_as_float((unsigned)(v >> 32)); }

static __device__ __forceinline__ unsigned smaddr(const void* p) {
    return (unsigned)__cvta_generic_to_shared(p);
}
#define CP16(dst, src)  asm volatile("cp.async.cg.shared.global [%0], [%1], 16;" :: "r"(dst), "l"(src))
#define CP_COMMIT()     asm volatile("cp.async.commit_group;" ::: "memory")
#define CP_WAIT1()      asm volatile("cp.async.wait_group 1;" ::: "memory")

// ---------------- kernel 1: fold query into kv_w (k half) ----------------
__global__ void k_wq(const float* __restrict__ q,
                     const float* __restrict__ kvw,
                     const float* __restrict__ kvb) {
    int w = blockIdx.x * (blockDim.x >> 5) + (threadIdx.x >> 5);
    int lane = threadIdx.x & 31;
    if (w < NHEADS * HID) {
        int h = w & (NHEADS - 1);
        int i = w >> 4;
        const float* wr = kvw + (size_t)i * (2 * HID) + h * 64;
        const float* qr = q + h * 64;
        float s = qr[lane] * wr[lane] + qr[lane + 32] * wr[lane + 32];
        #pragma unroll
        for (int o = 16; o; o >>= 1) s += __shfl_xor_sync(0xffffffffu, s, o);
        if (lane == 0) g_wq[h * HID + i] = 0.125f * s;   // scale = 1/sqrt(64)
    }
    if (blockIdx.x == 0 && threadIdx.x < NHEADS) {
        int h = threadIdx.x;
        float s = 0.f;
        for (int d = 0; d < 64; d++) s += q[h * 64 + d] * kvb[h * 64 + d];
        g_c[h] = 0.125f * s;
    }
}

// ---------------- kernel 2: logits[b,h,j] = hid[b,j,:] . wq[h,:] + c[h] ----------------
// 128 threads, 1 j-row each. hid staged via cp.async double-buffered k-chunks
// of 32 (coalesced gmem: 4 lines/warp-LDG). Padded smem (stride 36 floats ->
// bank step 4, conflict-free 4-phase LDS.128). 40KB smem -> 5 CTAs/SM.
#define LCH   32
#define NCH   (HID / LCH)
#define HPAD  36

__global__ void __launch_bounds__(128) k_logits(const float* __restrict__ hid) {
    __shared__ __align__(16) float hid_s[2][128][HPAD];
    __shared__ __align__(16) float wq_s[2][NHEADS][LCH];
    int tid = threadIdx.x;
    const float* hblk = hid + (size_t)blockIdx.x * 128 * HID;

    int kk = (tid & 7) * 4;
    int r0 = tid >> 3;          // 0..15

    ull acc[NHEADS];
    #pragma unroll
    for (int h = 0; h < NHEADS; h++) acc[h] = 0ull;

    // preload chunk 0 into buf 0
    {
        int kc = 0;
        #pragma unroll
        for (int p = 0; p < 8; p++) {
            int row = p * 16 + r0;
            CP16(smaddr(&hid_s[0][row][kk]), hblk + (size_t)row * HID + kc + kk);
        }
        CP16(smaddr(&wq_s[0][r0][kk]), g_wq + r0 * HID + kc + kk);
        CP_COMMIT();
    }

    for (int c = 0; c < NCH; c++) {
        if (c + 1 < NCH) {
            int kc = (c + 1) * LCH;
            int buf = (c + 1) & 1;
            #pragma unroll
            for (int p = 0; p < 8; p++) {
                int row = p * 16 + r0;
                CP16(smaddr(&hid_s[buf][row][kk]), hblk + (size_t)row * HID + kc + kk);
            }
            CP16(smaddr(&wq_s[buf][r0][kk]), g_wq + r0 * HID + kc + kk);
        }
        CP_COMMIT();
        CP_WAIT1();
        __syncthreads();

        int buf = c & 1;
        #pragma unroll
        for (int k = 0; k < LCH; k += 8) {
            ulonglong2 h0 = *(const ulonglong2*)&hid_s[buf][tid][k];
            ulonglong2 h1 = *(const ulonglong2*)&hid_s[buf][tid][k + 4];
            #pragma unroll
            for (int h = 0; h < NHEADS; h++) {
                ulonglong2 w0 = *(const ulonglong2*)&wq_s[buf][h][k];
                ulonglong2 w1 = *(const ulonglong2*)&wq_s[buf][h][k + 4];
                FMA2(acc[h], h0.x, w0.x);
                FMA2(acc[h], h0.y, w0.y);
                FMA2(acc[h], h1.x, w1.x);
                FMA2(acc[h], h1.y, w1.y);
            }
        }
        __syncthreads();
    }

    size_t j = (size_t)blockIdx.x * 128 + tid;
    int b  = (int)(j >> 11);
    int jj = (int)(j & 2047);
    #pragma unroll
    for (int h = 0; h < NHEADS; h++) {
        g_logits[((size_t)(b * NHEADS + h)) * TT + jj] = f2_lo(acc[h]) + f2_hi(acc[h]) + g_c[h];
    }
}

// ---------------- kernel 3: softmax over j per (b,h), mask-aware, in-place ----------------
__global__ void __launch_bounds__(256) k_softmax(const int* __restrict__ mask) {
    int bh = blockIdx.x;
    int b  = bh >> 4;
    float* row = g_logits + (size_t)bh * TT;
    const int* mrow = mask + (size_t)b * TT;
    int tid = threadIdx.x;

    float x[8];
    float mx = -1e30f;
    #pragma unroll
    for (int r = 0; r < 8; r++) {
        int j = tid + r * 256;
        float v = row[j];
        if (mrow[j] == 0) v = -1e30f;
        x[r] = v;
        mx = fmaxf(mx, v);
    }
    __shared__ float red[8];
    #pragma unroll
    for (int o = 16; o; o >>= 1) mx = fmaxf(mx, __shfl_xor_sync(0xffffffffu, mx, o));
    if ((tid & 31) == 0) red[tid >> 5] = mx;
    __syncthreads();
    mx = red[0];
    #pragma unroll
    for (int w = 1; w < 8; w++) mx = fmaxf(mx, red[w]);

    float sum = 0.f;
    #pragma unroll
    for (int r = 0; r < 8; r++) { float e = __expf(x[r] - mx); x[r] = e; sum += e; }
    #pragma unroll
    for (int o = 16; o; o >>= 1) sum += __shfl_xor_sync(0xffffffffu, sum, o);
    __syncthreads();
    if ((tid & 31) == 0) red[tid >> 5] = sum;
    __syncthreads();
    sum = red[0] + red[1] + red[2] + red[3] + red[4] + red[5] + red[6] + red[7];
    float inv = __fdividef(1.f, sum);
    #pragma unroll
    for (int r = 0; r < 8; r++) row[tid + r * 256] = x[r] * inv;
}

// ---------------- kernel 4: partial pooled[b,h,:] = sum_j attn * hid over a j-slice ----------------
// 256 threads, 4 i each (32 ull acc = 64 regs -> 16 warps/SM). attn broadcast
// LDS.128 head-pairs; depth-2 j prefetch of hidden.
__global__ void __launch_bounds__(256) k_pool(const float* __restrict__ hid) {
    int slice = blockIdx.x;       // 16 slices of 128 j
    int b     = blockIdx.y;
    int j0    = slice * 128;
    __shared__ __align__(16) ull attn_s[128][NHEADS];   // 16 KB, value duplicated in both halves
    int tid = threadIdx.x;

    #pragma unroll
    for (int t = 0; t < 8; t++) {
        int idx = t * 256 + tid;
        int jloc = idx & 127;
        int h    = idx >> 7;
        float a = g_logits[((size_t)(b * NHEADS + h)) * TT + j0 + jloc];
        unsigned u = __float_as_uint(a);
        attn_s[jloc][h] = ((ull)u << 32) | u;
    }
    __syncthreads();

    int i0 = tid * 4;
    const float* hbase = hid + ((size_t)b * TT + j0) * HID + i0;

    ull acc[32];   // [h][2]  (4 i = 2 f32x2 per head)
    #pragma unroll
    for (int t = 0; t < 32; t++) acc[t] = 0ull;

    ulonglong2 c0 = *(const ulonglong2*)(hbase);
    ulonglong2 c1 = *(const ulonglong2*)(hbase + HID);

    for (int j = 0; j < 128; j++) {
        ulonglong2 u0 = c0;
        c0 = c1;
        if (j < 126) c1 = *(const ulonglong2*)(hbase + (size_t)(j + 2) * HID);
        #pragma unroll
        for (int p = 0; p < 8; p++) {                 // head pairs
            ulonglong2 ap = *(const ulonglong2*)&attn_s[j][2 * p];
            FMA2(acc[4 * p + 0], ap.x, u0.x);
            FMA2(acc[4 * p + 1], ap.x, u0.y);
            FMA2(acc[4 * p + 2], ap.y, u0.x);
            FMA2(acc[4 * p + 3], ap.y, u0.y);
        }
    }

    float* pbase = g_partial + (((size_t)slice * BB + b) * NHEADS) * HID + i0;
    #pragma unroll
    for (int h = 0; h < NHEADS; h++) {
        float4 o;
        o.x = f2_lo(acc[2 * h]);     o.y = f2_hi(acc[2 * h]);
        o.z = f2_lo(acc[2 * h + 1]); o.w = f2_hi(acc[2 * h + 1]);
        *(float4*)(pbase + (size_t)h * HID) = o;
    }
}

// ---------------- kernel 5: reduce partials + per-head V projection ----------------
__global__ void __launch_bounds__(256) k_outv(const float* __restrict__ kvw,
                                              const float* __restrict__ kvb) {
    int bh = blockIdx.x;
    int b = bh >> 4;
    int h = bh & 15;
    __shared__ float pooled_s[HID];
    __shared__ float red[4][64];
    int tid = threadIdx.x;
    int i0 = tid * 4;

    float4 s = make_float4(0.f, 0.f, 0.f, 0.f);
    for (int sl = 0; sl < 16; sl++) {
        float4 v = *(const float4*)(g_partial + (((size_t)sl * BB + b) * NHEADS + h) * HID + i0);
        s.x += v.x; s.y += v.y; s.z += v.z; s.w += v.w;
    }
    *(float4*)(pooled_s + i0) = s;
    __syncthreads();

    int d  = tid & 63;
    int qq = tid >> 6;
    const float* wcol = kvw + HID + h * 64 + d;   // v half; row stride 2*HID
    float acc = 0.f;
    int ibeg = qq * 256;
    #pragma unroll 4
    for (int i = ibeg; i < ibeg + 256; i++)
        acc += pooled_s[i] * __ldg(wcol + (size_t)i * (2 * HID));
    red[qq][d] = acc;
    __syncthreads();
    if (tid < 64)
        g_outv[b * HID + h * 64 + tid] =
            red[0][tid] + red[1][tid] + red[2][tid] + red[3][tid] + kvb[HID + h * 64 + tid];
}

// ---------------- kernel 6: final GEMM [32,1024] x [1024,1024], c-sliced ----------------
__global__ void __launch_bounds__(256) k_final(const float* __restrict__ outw) {
    int p0 = blockIdx.x * 128;
    int c0 = blockIdx.y * 128;
    __shared__ float outv_s[32][128];
    int tid = threadIdx.x;
    for (int t = tid; t < 32 * 128; t += 256) {
        int bb2 = t >> 7;
        int cc  = t & 127;
        outv_s[bb2][cc] = g_outv[bb2 * HID + c0 + cc];
    }
    __syncthreads();

    int p   = tid & 127;
    int bh2 = tid >> 7;   // 0/1 -> 16 batches each
    float acc[16];
    #pragma unroll
    for (int n = 0; n < 16; n++) acc[n] = 0.f;

    for (int cc = 0; cc < 128; cc++) {
        float w = __ldg(outw + (size_t)(c0 + cc) * 1024 + p0 + p);
        #pragma unroll
        for (int n = 0; n < 16; n++) acc[n] += outv_s[bh2 * 16 + n][cc] * w;
    }
    #pragma unroll
    for (int n = 0; n < 16; n++)
        g_fpart[((size_t)blockIdx.y * BB + bh2 * 16 + n) * 1024 + p0 + p] = acc[n];
}

__global__ void k_finred(const float* __restrict__ outb, float* __restrict__ out) {
    int idx = blockIdx.x * 256 + threadIdx.x;   // 32768 outputs
    int b = idx >> 10;
    int p = idx & 1023;
    float s = outb[p];
    #pragma unroll
    for (int cs = 0; cs < 8; cs++) s += g_fpart[((size_t)cs * BB + b) * 1024 + p];
    out[idx] = s;
}

// ---------------- launch ----------------
extern "C" void kernel_launch(void* const* d_in, const int* in_sizes, int n_in,
                              void* d_out, int out_size) {
    const float* hid  = (const float*)d_in[0];
    const int*   mask = (const int*)  d_in[1];
    const float* kvw  = (const float*)d_in[2];
    const float* kvb  = (const float*)d_in[3];
    const float* outw = (const float*)d_in[4];
    const float* outb = (const float*)d_in[5];
    const float* q    = (const float*)d_in[6];
    float* out = (float*)d_out;

    k_wq     <<<2048, 256>>>(q, kvw, kvb);
    k_logits <<<512, 128>>>(hid);
    k_softmax<<<512, 256>>>(mask);
    k_pool   <<<dim3(16, 32), 256>>>(hid);
    k_outv   <<<512, 256>>>(kvw, kvb);
    k_final  <<<dim3(8, 8), 256>>>(outw);
    k_finred <<<128, 256>>>(outb, out);
}

// round 4
// speedup vs baseline: 1.5954x; 1.2665x over previous
#include <cuda_runtime.h>
#include <cstdint>

#define NHEADS 16
#define HID    1024
#define TT     2048
#define BB     32

typedef unsigned long long ull;

// ---------------- device scratch (no allocations allowed) ----------------
__device__ float g_wq[NHEADS * HID];                  // folded q @ kv_w (k half), incl. scale
__device__ float g_c[NHEADS];                         // folded q @ kv_b (k half)
__device__ float g_logits[BB * NHEADS * TT];          // 4 MB; reused in-place as attn
__device__ float g_partial[16 * BB * NHEADS * HID];   // 32 MB pass-2 partials
__device__ float g_outv[BB * HID];                    // pooled, v-projected [B, H]
__device__ float g_fpart[16 * BB * HID];              // final-GEMM c-slice partials

// packed f32x2 FMA (Blackwell; ptxas never emits FFMA2 from C++)
#define FMA2(c, a, b) asm("fma.rn.f32x2 %0, %1, %2, %0;" : "+l"(c) : "l"(a), "l"(b))

static __device__ __forceinline__ float f2_lo(ull v) { return __uint_as_float((unsigned)(v & 0xffffffffull)); }
static __device__ __forceinline__ float f2_hi(ull v) { return __uint_as_float((unsigned)(v >> 32)); }

static __device__ __forceinline__ unsigned smaddr(const void* p) {
    return (unsigned)__cvta_generic_to_shared(p);
}
#define CP16(dst, src)  asm volatile("cp.async.cg.shared.global [%0], [%1], 16;" :: "r"(dst), "l"(src))
#define CP_COMMIT()     asm volatile("cp.async.commit_group;" ::: "memory")
#define CP_WAIT1()      asm volatile("cp.async.wait_group 1;" ::: "memory")

// ---------------- kernel 1: fold query into kv_w (k half) ----------------
__global__ void k_wq(const float* __restrict__ q,
                     const float* __restrict__ kvw,
                     const float* __restrict__ kvb) {
    int w = blockIdx.x * (blockDim.x >> 5) + (threadIdx.x >> 5);
    int lane = threadIdx.x & 31;
    if (w < NHEADS * HID) {
        int h = w & (NHEADS - 1);
        int i = w >> 4;
        const float* wr = kvw + (size_t)i * (2 * HID) + h * 64;
        const float* qr = q + h * 64;
        float s = qr[lane] * wr[lane] + qr[lane + 32] * wr[lane + 32];
        #pragma unroll
        for (int o = 16; o; o >>= 1) s += __shfl_xor_sync(0xffffffffu, s, o);
        if (lane == 0) g_wq[h * HID + i] = 0.125f * s;   // scale = 1/sqrt(64)
    }
    if (blockIdx.x == 0 && threadIdx.x < NHEADS) {
        int h = threadIdx.x;
        float s = 0.f;
        for (int d = 0; d < 64; d++) s += q[h * 64 + d] * kvb[h * 64 + d];
        g_c[h] = 0.125f * s;
    }
}

// ---------------- kernel 2: logits[b,h,j] = hid[b,j,:] . wq[h,:] + c[h] ----------------
// 64 threads, TWO j-rows each (tid, tid+64) -> wq broadcasts amortized:
// per warp-8k: 128 FFMA2 (64 cyc) vs 48 LDS wavefronts => fma-bound.
// hid + wq staged via cp.async, double-buffered 32-k chunks.
#define LCH 32
__global__ void __launch_bounds__(64) k_logits(const float* __restrict__ hid) {
    __shared__ __align__(16) float hid_s[2][128][36];   // 36.9 KB, pad 36 -> conflict-free
    __shared__ __align__(16) float wq_s[2][NHEADS][LCH];
    int tid = threadIdx.x;
    const float* hblk = hid + (size_t)blockIdx.x * 128 * HID;
    int lrow = tid >> 3;          // 0..7
    int lcol = (tid & 7) * 4;     // 0..28

    ull acc0[NHEADS], acc1[NHEADS];
    #pragma unroll
    for (int h = 0; h < NHEADS; h++) { acc0[h] = 0ull; acc1[h] = 0ull; }

    // preload chunk 0 into buf 0
    #pragma unroll
    for (int p = 0; p < 16; p++)
        CP16(smaddr(&hid_s[0][p * 8 + lrow][lcol]), hblk + (size_t)(p * 8 + lrow) * HID + lcol);
    #pragma unroll
    for (int p = 0; p < 2; p++)
        CP16(smaddr(&wq_s[0][p * 8 + lrow][lcol]), g_wq + (p * 8 + lrow) * HID + lcol);
    CP_COMMIT();

    for (int c = 0; c < HID / LCH; c++) {
        if (c + 1 < HID / LCH) {
            int kc  = (c + 1) * LCH;
            int buf = (c + 1) & 1;
            #pragma unroll
            for (int p = 0; p < 16; p++)
                CP16(smaddr(&hid_s[buf][p * 8 + lrow][lcol]),
                     hblk + (size_t)(p * 8 + lrow) * HID + kc + lcol);
            #pragma unroll
            for (int p = 0; p < 2; p++)
                CP16(smaddr(&wq_s[buf][p * 8 + lrow][lcol]), g_wq + (p * 8 + lrow) * HID + kc + lcol);
        }
        CP_COMMIT();
        CP_WAIT1();
        __syncthreads();

        int buf = c & 1;
        const float* rA = hid_s[buf][tid];
        const float* rB = hid_s[buf][tid + 64];
        #pragma unroll
        for (int k = 0; k < LCH; k += 8) {
            ulonglong2 a0 = *(const ulonglong2*)(rA + k);
            ulonglong2 c0 = *(const ulonglong2*)(rA + k + 4);
            ulonglong2 a1 = *(const ulonglong2*)(rB + k);
            ulonglong2 c1 = *(const ulonglong2*)(rB + k + 4);
            #pragma unroll
            for (int h = 0; h < NHEADS; h++) {
                ulonglong2 w0 = *(const ulonglong2*)&wq_s[buf][h][k];
                ulonglong2 w1 = *(const ulonglong2*)&wq_s[buf][h][k + 4];
                FMA2(acc0[h], a0.x, w0.x);
                FMA2(acc0[h], a0.y, w0.y);
                FMA2(acc0[h], c0.x, w1.x);
                FMA2(acc0[h], c0.y, w1.y);
                FMA2(acc1[h], a1.x, w0.x);
                FMA2(acc1[h], a1.y, w0.y);
                FMA2(acc1[h], c1.x, w1.x);
                FMA2(acc1[h], c1.y, w1.y);
            }
        }
        __syncthreads();   // protect buffers before next iteration's cp.async
    }

    size_t jA = (size_t)blockIdx.x * 128 + tid;
    size_t jB = jA + 64;
    int bA = (int)(jA >> 11), ja = (int)(jA & 2047);
    int bB = (int)(jB >> 11), jb = (int)(jB & 2047);
    #pragma unroll
    for (int h = 0; h < NHEADS; h++) {
        float cc = g_c[h];
        g_logits[((size_t)(bA * NHEADS + h)) * TT + ja] = f2_lo(acc0[h]) + f2_hi(acc0[h]) + cc;
        g_logits[((size_t)(bB * NHEADS + h)) * TT + jb] = f2_lo(acc1[h]) + f2_hi(acc1[h]) + cc;
    }
}

// ---------------- kernel 3: softmax over j per (b,h), mask-aware, in-place ----------------
__global__ void __launch_bounds__(256) k_softmax(const int* __restrict__ mask, int b0) {
    int b  = b0 + (blockIdx.x >> 4);
    int bh = b * NHEADS + (blockIdx.x & 15);
    float* row = g_logits + (size_t)bh * TT;
    const int* mrow = mask + (size_t)b * TT;
    int tid = threadIdx.x;

    float x[8];
    float mx = -1e30f;
    #pragma unroll
    for (int r = 0; r < 8; r++) {
        int j = tid + r * 256;
        float v = row[j];
        if (mrow[j] == 0) v = -1e30f;
        x[r] = v;
        mx = fmaxf(mx, v);
    }
    __shared__ float red[8];
    #pragma unroll
    for (int o = 16; o; o >>= 1) mx = fmaxf(mx, __shfl_xor_sync(0xffffffffu, mx, o));
    if ((tid & 31) == 0) red[tid >> 5] = mx;
    __syncthreads();
    mx = red[0];
    #pragma unroll
    for (int w = 1; w < 8; w++) mx = fmaxf(mx, red[w]);

    float sum = 0.f;
    #pragma unroll
    for (int r = 0; r < 8; r++) { float e = __expf(x[r] - mx); x[r] = e; sum += e; }
    #pragma unroll
    for (int o = 16; o; o >>= 1) sum += __shfl_xor_sync(0xffffffffu, sum, o);
    __syncthreads();
    if ((tid & 31) == 0) red[tid >> 5] = sum;
    __syncthreads();
    sum = red[0] + red[1] + red[2] + red[3] + red[4] + red[5] + red[6] + red[7];
    float inv = __fdividef(1.f, sum);
    #pragma unroll
    for (int r = 0; r < 8; r++) row[tid + r * 256] = x[r] * inv;
}

// ---------------- kernel 4: partial pooled[b,h,:] = sum_j attn * hid over a j-slice ----------------
// hid staged via cp.async (2 x 8-row buffers, 64KB dynamic smem); compute is
// conflict-free LDS.128 + FFMA2. 256 threads, 4 i each.
__global__ void __launch_bounds__(256) k_pool(const float* __restrict__ hid, int b0) {
    extern __shared__ __align__(16) float hsm[];        // [2][8][1024]
    __shared__ __align__(16) ull attn_s[128][NHEADS];   // 16 KB duplicated f32x2
    int slice = blockIdx.x;       // 16 slices of 128 j
    int b     = b0 + blockIdx.y;
    int j0    = slice * 128;
    int tid   = threadIdx.x;

    const float* hbase = hid + ((size_t)b * TT + j0) * HID;

    // loader mapping: per 8-row stage, 2048 float4 over 256 threads = 8 each
    int lrow = tid >> 5;            // not used directly; linear map below

    // preload stage 0
    #pragma unroll
    for (int p = 0; p < 8; p++) {
        int idx  = p * 256 + tid;
        int row  = idx >> 8;
        int col  = (idx & 255) * 4;
        CP16(smaddr(hsm + row * 1024 + col), hbase + (size_t)row * HID + col);
    }
    CP_COMMIT();

    // attn stage (overlaps stage-0 fetch)
    #pragma unroll
    for (int t = 0; t < 8; t++) {
        int idx  = t * 256 + tid;
        int jloc = idx & 127;
        int h    = idx >> 7;
        float a = g_logits[((size_t)(b * NHEADS + h)) * TT + j0 + jloc];
        unsigned u = __float_as_uint(a);
        attn_s[jloc][h] = ((ull)u << 32) | u;
    }

    int i0 = tid * 4;
    ull acc[32];   // [h][2]
    #pragma unroll
    for (int t = 0; t < 32; t++) acc[t] = 0ull;

    for (int s = 0; s < 16; s++) {
        if (s + 1 < 16) {
            float* dstb = hsm + ((s + 1) & 1) * 8192;
            const float* srcb = hbase + (size_t)(s + 1) * 8 * HID;
            #pragma unroll
            for (int p = 0; p < 8; p++) {
                int idx = p * 256 + tid;
                int row = idx >> 8;
                int col = (idx & 255) * 4;
                CP16(smaddr(dstb + row * 1024 + col), srcb + (size_t)row * HID + col);
            }
        }
        CP_COMMIT();
        CP_WAIT1();
        __syncthreads();

        const float* buf = hsm + (s & 1) * 8192;
        #pragma unroll
        for (int jj = 0; jj < 8; jj++) {
            int j = s * 8 + jj;
            ulonglong2 u0 = *(const ulonglong2*)(buf + jj * 1024 + i0);
            #pragma unroll
            for (int p = 0; p < 8; p++) {
                ulonglong2 ap = *(const ulonglong2*)&attn_s[j][2 * p];
                FMA2(acc[4 * p + 0], ap.x, u0.x);
                FMA2(acc[4 * p + 1], ap.x, u0.y);
                FMA2(acc[4 * p + 2], ap.y, u0.x);
                FMA2(acc[4 * p + 3], ap.y, u0.y);
            }
        }
        __syncthreads();   // protect buffer before next cp.async overwrite
    }

    float* pbase = g_partial + (((size_t)slice * BB + b) * NHEADS) * HID + i0;
    #pragma unroll
    for (int h = 0; h < NHEADS; h++) {
        float4 o;
        o.x = f2_lo(acc[2 * h]);     o.y = f2_hi(acc[2 * h]);
        o.z = f2_lo(acc[2 * h + 1]); o.w = f2_hi(acc[2 * h + 1]);
        *(float4*)(pbase + (size_t)h * HID) = o;
    }
}

// ---------------- kernel 5: reduce partials + per-head V projection ----------------
__global__ void __launch_bounds__(256) k_outv(const float* __restrict__ kvw,
                                              const float* __restrict__ kvb) {
    int bh = blockIdx.x;
    int b = bh >> 4;
    int h = bh & 15;
    __shared__ float pooled_s[HID];
    __shared__ float red[4][64];
    int tid = threadIdx.x;
    int i0 = tid * 4;

    float4 s = make_float4(0.f, 0.f, 0.f, 0.f);
    for (int sl = 0; sl < 16; sl++) {
        float4 v = *(const float4*)(g_partial + (((size_t)sl * BB + b) * NHEADS + h) * HID + i0);
        s.x += v.x; s.y += v.y; s.z += v.z; s.w += v.w;
    }
    *(float4*)(pooled_s + i0) = s;
    __syncthreads();

    int d  = tid & 63;
    int qq = tid >> 6;
    const float* wcol = kvw + HID + h * 64 + d;   // v half; row stride 2*HID
    float acc = 0.f;
    int ibeg = qq * 256;
    #pragma unroll 4
    for (int i = ibeg; i < ibeg + 256; i++)
        acc += pooled_s[i] * __ldg(wcol + (size_t)i * (2 * HID));
    red[qq][d] = acc;
    __syncthreads();
    if (tid < 64)
        g_outv[b * HID + h * 64 + tid] =
            red[0][tid] + red[1][tid] + red[2][tid] + red[3][tid] + kvb[HID + h * 64 + tid];
}

// ---------------- kernel 6: final GEMM [32,1024] x [1024,1024], c-sliced ----------------
__global__ void __launch_bounds__(256) k_final(const float* __restrict__ outw) {
    int p0 = blockIdx.x * 128;
    int c0 = blockIdx.y * 64;
    __shared__ float outv_s[32][64];
    int tid = threadIdx.x;
    for (int t = tid; t < 32 * 64; t += 256) {
        int bb2 = t >> 6;
        int cc  = t & 63;
        outv_s[bb2][cc] = g_outv[bb2 * HID + c0 + cc];
    }
    __syncthreads();

    int p   = tid & 127;
    int bh2 = tid >> 7;   // 0/1 -> 16 batches each
    float acc[16];
    #pragma unroll
    for (int n = 0; n < 16; n++) acc[n] = 0.f;

    #pragma unroll 4
    for (int cc = 0; cc < 64; cc++) {
        float w = __ldg(outw + (size_t)(c0 + cc) * 1024 + p0 + p);
        #pragma unroll
        for (int n = 0; n < 16; n++) acc[n] += outv_s[bh2 * 16 + n][cc] * w;
    }
    #pragma unroll
    for (int n = 0; n < 16; n++)
        g_fpart[((size_t)blockIdx.y * BB + bh2 * 16 + n) * 1024 + p0 + p] = acc[n];
}

__global__ void k_finred(const float* __restrict__ outb, float* __restrict__ out) {
    int idx = blockIdx.x * 256 + threadIdx.x;   // 32768 outputs
    int b = idx >> 10;
    int p = idx & 1023;
    float s = outb[p];
    #pragma unroll
    for (int cs = 0; cs < 16; cs++) s += g_fpart[((size_t)cs * BB + b) * 1024 + p];
    out[idx] = s;
}

// ---------------- launch ----------------
extern "C" void kernel_launch(void* const* d_in, const int* in_sizes, int n_in,
                              void* d_out, int out_size) {
    const float* hid  = (const float*)d_in[0];
    const int*   mask = (const int*)  d_in[1];
    const float* kvw  = (const float*)d_in[2];
    const float* kvb  = (const float*)d_in[3];
    const float* outw = (const float*)d_in[4];
    const float* outb = (const float*)d_in[5];
    const float* q    = (const float*)d_in[6];
    float* out = (float*)d_out;

    cudaFuncSetAttribute(k_pool, cudaFuncAttributeMaxDynamicSharedMemorySize, 65536);

    k_wq     <<<2048, 256>>>(q, kvw, kvb);
    k_logits <<<512, 64>>>(hid);
    // reverse batch order: pool's first chunks re-read hid still resident in L2
    for (int c = 3; c >= 0; c--) {
        int b0 = c * 8;
        k_softmax<<<128, 256>>>(mask, b0);
        k_pool   <<<dim3(16, 8), 256, 65536>>>(hid, b0);
    }
    k_outv   <<<512, 256>>>(kvw, kvb);
    k_final  <<<dim3(8, 16), 256>>>(outw);
    k_finred <<<128, 256>>>(outb, out);
}